// round 3
// baseline (speedup 1.0000x reference)
#include <cuda_runtime.h>
#include <cstdint>
#include <cstddef>

#define N_NODES  100000
#define N_EDGES  1600000
#define DIM      128
#define N_GRAPHS 512

// ---------------- scratch (static device globals; no allocation) ----------------
__device__ __align__(16) float g_h[(size_t)N_NODES * DIM];    // x @ W (per layer)
__device__ __align__(16) float g_agg[(size_t)N_NODES * DIM];  // aggregated output
__device__ __align__(16) float g_dinv[N_NODES];
__device__ __align__(16) int   g_cnt[N_NODES];                // in-degree (real edges)
__device__ __align__(16) int   g_off[N_NODES];                // CSR offsets
__device__ __align__(16) int   g_cur[N_NODES];                // fill cursors
__device__ __align__(16) int   g_csr_src[N_EDGES];
__device__ __align__(16) float g_csr_w[N_EDGES];
__device__ __align__(16) float g_gsum[N_GRAPHS * DIM];
__device__ __align__(16) float g_gcnt[N_GRAPHS];

// ---------------- setup kernels ----------------
__global__ void k_zero() {
    int i = blockIdx.x * blockDim.x + threadIdx.x;
    if (i < N_NODES) g_cnt[i] = 0;
    if (i < N_GRAPHS * DIM) g_gsum[i] = 0.f;
    if (i < N_GRAPHS) g_gcnt[i] = 0.f;
}

__global__ void k_degree(const int* __restrict__ ei) {
    int e = blockIdx.x * blockDim.x + threadIdx.x;
    if (e < N_EDGES) {
        int d = ei[N_EDGES + e];
        if ((unsigned)d < N_NODES) atomicAdd(&g_cnt[d], 1);
    }
}

// Single-block exclusive scan of g_cnt -> g_off, g_cur.
__global__ void k_scan() {
    __shared__ int warp_sums[32];
    __shared__ int s_carry;
    int t = threadIdx.x, lane = t & 31, wid = t >> 5;
    if (t == 0) s_carry = 0;
    __syncthreads();
    for (int base = 0; base < N_NODES; base += 4096) {
        int i0 = base + t * 4;
        int v[4];
#pragma unroll
        for (int q = 0; q < 4; q++) {
            int i = i0 + q;
            v[q] = (i < N_NODES) ? g_cnt[i] : 0;
        }
        int tsum = v[0] + v[1] + v[2] + v[3];
        int x = tsum;
#pragma unroll
        for (int s = 1; s < 32; s <<= 1) {
            int y = __shfl_up_sync(0xffffffffu, x, s);
            if (lane >= s) x += y;
        }
        if (lane == 31) warp_sums[wid] = x;
        __syncthreads();
        if (wid == 0) {
            int ws = warp_sums[lane];
            int xx = ws;
#pragma unroll
            for (int s = 1; s < 32; s <<= 1) {
                int y = __shfl_up_sync(0xffffffffu, xx, s);
                if (lane >= s) xx += y;
            }
            warp_sums[lane] = xx - ws;  // exclusive
        }
        __syncthreads();
        int run = s_carry + warp_sums[wid] + (x - tsum);
#pragma unroll
        for (int q = 0; q < 4; q++) {
            int i = i0 + q;
            if (i < N_NODES) { g_off[i] = run; g_cur[i] = run; }
            run += v[q];
        }
        __syncthreads();
        if (t == 1023) s_carry += warp_sums[31] + x;
        __syncthreads();
    }
}

__global__ void k_dinv() {
    int i = blockIdx.x * blockDim.x + threadIdx.x;
    if (i < N_NODES) g_dinv[i] = rsqrtf((float)g_cnt[i] + 1.0f);  // +1 self loop
}

__global__ void k_fill(const int* __restrict__ ei) {
    int e = blockIdx.x * blockDim.x + threadIdx.x;
    if (e < N_EDGES) {
        int s = ei[e];
        int d = ei[N_EDGES + e];
        if ((unsigned)s < N_NODES && (unsigned)d < N_NODES) {
            int pos = atomicAdd(&g_cur[d], 1);
            if ((unsigned)pos < N_EDGES) {
                g_csr_src[pos] = s;
                g_csr_w[pos] = g_dinv[s] * g_dinv[d];
            }
        }
    }
}

// ---------------- GEMM: g_h = act(in + bias) @ W  (in = x or g_agg) ----------------
// BM=64 rows/block, BN=128, BK=16, 256 threads, 4x8 micro-tile, plain FFMA.
__global__ __launch_bounds__(256) void k_gemm(const float* __restrict__ xin,
                                              const float* __restrict__ W,
                                              const float* __restrict__ bias,
                                              int use_agg_in, int do_relu) {
    __shared__ __align__(16) float As[16][68];
    __shared__ __align__(16) float Bs[16][132];
    const float* in = use_agg_in ? g_agg : xin;
    int r0 = blockIdx.x * 64;
    int tid = threadIdx.x;
    int tm = (tid >> 4) << 2;   // 0..60
    int tn = (tid & 15) << 3;   // 0..120
    int arow = tid >> 2;        // 0..63
    int acol = (tid & 3) << 2;  // 0,4,8,12
    bool arow_ok = (r0 + arow) < N_NODES;
    const float4* inrow = (const float4*)(in + (size_t)(r0 + arow) * DIM);

    float acc[4][8];
#pragma unroll
    for (int i = 0; i < 4; i++)
#pragma unroll
        for (int j = 0; j < 8; j++) acc[i][j] = 0.f;

    int br1 = tid >> 5, bc1 = (tid & 31) << 2;

    for (int kb = 0; kb < DIM; kb += 16) {
        float4 av = make_float4(0.f, 0.f, 0.f, 0.f);
        if (arow_ok) av = inrow[(kb + acol) >> 2];
        if (bias) {
            float4 bv = *(const float4*)(bias + kb + acol);
            av.x += bv.x; av.y += bv.y; av.z += bv.z; av.w += bv.w;
        }
        if (do_relu) {
            av.x = fmaxf(av.x, 0.f); av.y = fmaxf(av.y, 0.f);
            av.z = fmaxf(av.z, 0.f); av.w = fmaxf(av.w, 0.f);
        }
        As[acol + 0][arow] = av.x;
        As[acol + 1][arow] = av.y;
        As[acol + 2][arow] = av.z;
        As[acol + 3][arow] = av.w;
        float4 w0 = *(const float4*)(W + (kb + br1) * DIM + bc1);
        float4 w1 = *(const float4*)(W + (kb + br1 + 8) * DIM + bc1);
        *(float4*)&Bs[br1][bc1] = w0;
        *(float4*)&Bs[br1 + 8][bc1] = w1;
        __syncthreads();
#pragma unroll
        for (int kk = 0; kk < 16; kk++) {
            float4 a = *(const float4*)&As[kk][tm];
            float4 b0 = *(const float4*)&Bs[kk][tn];
            float4 b1 = *(const float4*)&Bs[kk][tn + 4];
            float am[4] = {a.x, a.y, a.z, a.w};
            float bn[8] = {b0.x, b0.y, b0.z, b0.w, b1.x, b1.y, b1.z, b1.w};
#pragma unroll
            for (int i = 0; i < 4; i++)
#pragma unroll
                for (int j = 0; j < 8; j++)
                    acc[i][j] = fmaf(am[i], bn[j], acc[i][j]);
        }
        __syncthreads();
    }
#pragma unroll
    for (int i = 0; i < 4; i++) {
        int row = r0 + tm + i;
        if (row < N_NODES) {
            float* dst = g_h + (size_t)row * DIM + tn;
            *(float4*)(dst + 0) = make_float4(acc[i][0], acc[i][1], acc[i][2], acc[i][3]);
            *(float4*)(dst + 4) = make_float4(acc[i][4], acc[i][5], acc[i][6], acc[i][7]);
        }
    }
}

// ---------------- edge aggregation: one warp per destination node ----------------
__global__ __launch_bounds__(256) void k_agg() {
    int n = (blockIdx.x * blockDim.x + threadIdx.x) >> 5;
    int lane = threadIdx.x & 31;
    if (n >= N_NODES) return;
    const float4* h4 = (const float4*)g_h;
    float dn = g_dinv[n];
    float sw = dn * dn;
    float4 a = h4[(size_t)n * 32 + lane];
    float4 acc;
    acc.x = sw * a.x; acc.y = sw * a.y; acc.z = sw * a.z; acc.w = sw * a.w;
    int j = g_off[n];
    int end = j + g_cnt[n];
    for (; j + 4 <= end; j += 4) {
        int s0 = g_csr_src[j], s1 = g_csr_src[j + 1];
        int s2 = g_csr_src[j + 2], s3 = g_csr_src[j + 3];
        float w0 = g_csr_w[j], w1 = g_csr_w[j + 1];
        float w2 = g_csr_w[j + 2], w3 = g_csr_w[j + 3];
        float4 v0 = h4[(size_t)s0 * 32 + lane];
        float4 v1 = h4[(size_t)s1 * 32 + lane];
        float4 v2 = h4[(size_t)s2 * 32 + lane];
        float4 v3 = h4[(size_t)s3 * 32 + lane];
        acc.x += w0 * v0.x; acc.y += w0 * v0.y; acc.z += w0 * v0.z; acc.w += w0 * v0.w;
        acc.x += w1 * v1.x; acc.y += w1 * v1.y; acc.z += w1 * v1.z; acc.w += w1 * v1.w;
        acc.x += w2 * v2.x; acc.y += w2 * v2.y; acc.z += w2 * v2.z; acc.w += w2 * v2.w;
        acc.x += w3 * v3.x; acc.y += w3 * v3.y; acc.z += w3 * v3.z; acc.w += w3 * v3.w;
    }
    for (; j < end; j++) {
        int s = g_csr_src[j];
        float w = g_csr_w[j];
        float4 v = h4[(size_t)s * 32 + lane];
        acc.x += w * v.x; acc.y += w * v.y; acc.z += w * v.z; acc.w += w * v.w;
    }
    ((float4*)g_agg)[(size_t)n * 32 + lane] = acc;
}

// ---------------- readout: segmented sum over sorted batch ids ----------------
#define NPB 256
__global__ void k_readout(const int* __restrict__ batch) {
    int d = threadIdx.x;  // 128 threads, one dim each
    int n0 = blockIdx.x * NPB;
    if (n0 >= N_NODES) return;
    int n1 = n0 + NPB;
    if (n1 > N_NODES) n1 = N_NODES;
    int curb = batch[n0];
    if ((unsigned)curb >= N_GRAPHS) curb = 0;
    float acc = 0.f;
    int c = 0;
    for (int n = n0; n < n1; n++) {
        int b = batch[n];
        if ((unsigned)b >= N_GRAPHS) b = 0;
        if (b != curb) {
            atomicAdd(&g_gsum[curb * DIM + d], acc);
            if (d == 0) atomicAdd(&g_gcnt[curb], (float)c);
            acc = 0.f; c = 0; curb = b;
        }
        acc += g_agg[(size_t)n * DIM + d];
        c++;
    }
    atomicAdd(&g_gsum[curb * DIM + d], acc);
    if (d == 0) atomicAdd(&g_gcnt[curb], (float)c);
}

__global__ void k_final(const float* __restrict__ b3, float* __restrict__ out) {
    int i = blockIdx.x * blockDim.x + threadIdx.x;
    if (i < N_GRAPHS * DIM) {
        int g = i >> 7, d = i & 127;
        float c = g_gcnt[g];
        out[i] = (g_gsum[i] + c * b3[d]) / fmaxf(c, 1.0f);
    }
}

// ---------------- launch ----------------
extern "C" void kernel_launch(void* const* d_in, const int* in_sizes, int n_in,
                              void* d_out, int out_size) {
    (void)in_sizes; (void)n_in; (void)out_size;
    const float* x     = (const float*)d_in[0];
    const int*   ei    = (const int*)d_in[1];     // int32 (JAX x64 disabled)
    const int*   batch = (const int*)d_in[2];     // int32
    const float* W1    = (const float*)d_in[3];
    const float* b1    = (const float*)d_in[4];
    const float* W2    = (const float*)d_in[5];
    const float* b2    = (const float*)d_in[6];
    const float* W3    = (const float*)d_in[7];
    const float* b3    = (const float*)d_in[8];
    float* out = (float*)d_out;

    k_zero<<<(N_NODES + 255) / 256, 256>>>();
    k_degree<<<(N_EDGES + 255) / 256, 256>>>(ei);
    k_scan<<<1, 1024>>>();
    k_dinv<<<(N_NODES + 255) / 256, 256>>>();
    k_fill<<<(N_EDGES + 255) / 256, 256>>>(ei);

    int gemm_blocks = (N_NODES + 63) / 64;
    int agg_blocks = (N_NODES * 32 + 255) / 256;

    // layer 1
    k_gemm<<<gemm_blocks, 256>>>(x, W1, nullptr, 0, 0);
    k_agg<<<agg_blocks, 256>>>();
    // layer 2 (bias1 + relu fused into operand load)
    k_gemm<<<gemm_blocks, 256>>>(x, W2, b1, 1, 1);
    k_agg<<<agg_blocks, 256>>>();
    // layer 3 (bias2 + relu fused into operand load)
    k_gemm<<<gemm_blocks, 256>>>(x, W3, b2, 1, 1);
    k_agg<<<agg_blocks, 256>>>();

    k_readout<<<(N_NODES + NPB - 1) / NPB, 128>>>(batch);
    k_final<<<(N_GRAPHS * DIM + 255) / 256, 256>>>(b3, out);
}

// round 4
// speedup vs baseline: 1.0797x; 1.0797x over previous
#include <cuda_runtime.h>
#include <cstdint>
#include <cstddef>

#define N_NODES  100000
#define N_EDGES  1600000
#define DIM      128
#define N_GRAPHS 512

// ---------------- scratch (static device globals; no allocation) ----------------
__device__ __align__(16) float g_h[(size_t)N_NODES * DIM];
__device__ __align__(16) float g_agg[(size_t)N_NODES * DIM];
__device__ __align__(16) float g_dinv[N_NODES];
__device__ __align__(16) int   g_cnt[N_NODES];
__device__ __align__(16) int   g_off[N_NODES];
__device__ __align__(16) int   g_cur[N_NODES];
__device__ __align__(16) int   g_csr_src[N_EDGES];
__device__ __align__(16) float g_csr_w[N_EDGES];
__device__ __align__(16) float g_gsum[N_GRAPHS * DIM];
__device__ __align__(16) float g_gcnt[N_GRAPHS];

// ---------------- packed f32x2 helpers ----------------
__device__ __forceinline__ unsigned long long pack2(float x, float y) {
    unsigned long long r;
    asm("mov.b64 %0, {%1, %2};" : "=l"(r) : "f"(x), "f"(y));
    return r;
}
__device__ __forceinline__ unsigned long long ffma2(unsigned long long a,
                                                    unsigned long long b,
                                                    unsigned long long c) {
    unsigned long long d;
    asm("fma.rn.f32x2 %0, %1, %2, %3;" : "=l"(d) : "l"(a), "l"(b), "l"(c));
    return d;
}

// ---------------- setup kernels ----------------
__global__ void k_zero() {
    int i = blockIdx.x * blockDim.x + threadIdx.x;
    if (i < N_NODES) g_cnt[i] = 0;
    if (i < N_GRAPHS * DIM) g_gsum[i] = 0.f;
    if (i < N_GRAPHS) g_gcnt[i] = 0.f;
}

__global__ void k_degree(const int* __restrict__ ei) {
    int e = blockIdx.x * blockDim.x + threadIdx.x;
    if (e < N_EDGES) {
        int d = ei[N_EDGES + e];
        if ((unsigned)d < N_NODES) atomicAdd(&g_cnt[d], 1);
    }
}

// Single-block exclusive scan of g_cnt -> g_off, g_cur.
__global__ void k_scan() {
    __shared__ int warp_sums[32];
    __shared__ int s_carry;
    int t = threadIdx.x, lane = t & 31, wid = t >> 5;
    if (t == 0) s_carry = 0;
    __syncthreads();
    for (int base = 0; base < N_NODES; base += 4096) {
        int i0 = base + t * 4;
        int v[4];
#pragma unroll
        for (int q = 0; q < 4; q++) {
            int i = i0 + q;
            v[q] = (i < N_NODES) ? g_cnt[i] : 0;
        }
        int tsum = v[0] + v[1] + v[2] + v[3];
        int x = tsum;
#pragma unroll
        for (int s = 1; s < 32; s <<= 1) {
            int y = __shfl_up_sync(0xffffffffu, x, s);
            if (lane >= s) x += y;
        }
        if (lane == 31) warp_sums[wid] = x;
        __syncthreads();
        if (wid == 0) {
            int ws = warp_sums[lane];
            int xx = ws;
#pragma unroll
            for (int s = 1; s < 32; s <<= 1) {
                int y = __shfl_up_sync(0xffffffffu, xx, s);
                if (lane >= s) xx += y;
            }
            warp_sums[lane] = xx - ws;
        }
        __syncthreads();
        int run = s_carry + warp_sums[wid] + (x - tsum);
#pragma unroll
        for (int q = 0; q < 4; q++) {
            int i = i0 + q;
            if (i < N_NODES) { g_off[i] = run; g_cur[i] = run; }
            run += v[q];
        }
        __syncthreads();
        if (t == 1023) s_carry += warp_sums[31] + x;
        __syncthreads();
    }
}

__global__ void k_dinv() {
    int i = blockIdx.x * blockDim.x + threadIdx.x;
    if (i < N_NODES) g_dinv[i] = rsqrtf((float)g_cnt[i] + 1.0f);
}

__global__ void k_fill(const int* __restrict__ ei) {
    int e = blockIdx.x * blockDim.x + threadIdx.x;
    if (e < N_EDGES) {
        int s = ei[e];
        int d = ei[N_EDGES + e];
        if ((unsigned)s < N_NODES && (unsigned)d < N_NODES) {
            int pos = atomicAdd(&g_cur[d], 1);
            if ((unsigned)pos < N_EDGES) {
                g_csr_src[pos] = s;
                g_csr_w[pos] = g_dinv[s] * g_dinv[d];
            }
        }
    }
}

// ---------------- GEMM: g_h = act(in + bias) @ W, f32x2 packed FMAs ----------------
// BM=64 rows/block, BN=128, BK=16, 256 threads, 4x8 micro-tile.
__global__ __launch_bounds__(256) void k_gemm(const float* __restrict__ xin,
                                              const float* __restrict__ W,
                                              const float* __restrict__ bias,
                                              int use_agg_in, int do_relu) {
    __shared__ __align__(16) unsigned long long As2[16][66];  // (a,a) pairs, [k][m]
    __shared__ __align__(16) float Bs[16][128];               // [k][n]
    const float* in = use_agg_in ? g_agg : xin;
    int r0 = blockIdx.x * 64;
    int tid = threadIdx.x;
    int tm = (tid >> 4) << 2;   // 0..60
    int tn = (tid & 15) << 3;   // 0..120
    int arow = tid >> 2;        // 0..63
    int acol = (tid & 3) << 2;  // 0,4,8,12
    bool arow_ok = (r0 + arow) < N_NODES;
    const float4* inrow = (const float4*)(in + (size_t)(r0 + arow) * DIM);

    unsigned long long acc[4][4];
#pragma unroll
    for (int i = 0; i < 4; i++)
#pragma unroll
        for (int p = 0; p < 4; p++) acc[i][p] = 0ull;

    for (int kb = 0; kb < DIM; kb += 16) {
        float4 av = make_float4(0.f, 0.f, 0.f, 0.f);
        if (arow_ok) av = inrow[(kb + acol) >> 2];
        if (bias) {
            float4 bv = *(const float4*)(bias + kb + acol);
            av.x += bv.x; av.y += bv.y; av.z += bv.z; av.w += bv.w;
        }
        if (do_relu) {
            av.x = fmaxf(av.x, 0.f); av.y = fmaxf(av.y, 0.f);
            av.z = fmaxf(av.z, 0.f); av.w = fmaxf(av.w, 0.f);
        }
        As2[acol + 0][arow] = pack2(av.x, av.x);
        As2[acol + 1][arow] = pack2(av.y, av.y);
        As2[acol + 2][arow] = pack2(av.z, av.z);
        As2[acol + 3][arow] = pack2(av.w, av.w);
        const float4* Wv = (const float4*)(W + kb * DIM);
        float4* Bv = (float4*)(&Bs[0][0]);
        Bv[tid] = Wv[tid];
        Bv[tid + 256] = Wv[tid + 256];
        __syncthreads();
#pragma unroll
        for (int kk = 0; kk < 16; kk++) {
            ulonglong2 a01 = *(const ulonglong2*)&As2[kk][tm];
            ulonglong2 a23 = *(const ulonglong2*)&As2[kk][tm + 2];
            ulonglong2 b01 = *(const ulonglong2*)&Bs[kk][tn];
            ulonglong2 b23 = *(const ulonglong2*)&Bs[kk][tn + 4];
            acc[0][0] = ffma2(a01.x, b01.x, acc[0][0]);
            acc[0][1] = ffma2(a01.x, b01.y, acc[0][1]);
            acc[0][2] = ffma2(a01.x, b23.x, acc[0][2]);
            acc[0][3] = ffma2(a01.x, b23.y, acc[0][3]);
            acc[1][0] = ffma2(a01.y, b01.x, acc[1][0]);
            acc[1][1] = ffma2(a01.y, b01.y, acc[1][1]);
            acc[1][2] = ffma2(a01.y, b23.x, acc[1][2]);
            acc[1][3] = ffma2(a01.y, b23.y, acc[1][3]);
            acc[2][0] = ffma2(a23.x, b01.x, acc[2][0]);
            acc[2][1] = ffma2(a23.x, b01.y, acc[2][1]);
            acc[2][2] = ffma2(a23.x, b23.x, acc[2][2]);
            acc[2][3] = ffma2(a23.x, b23.y, acc[2][3]);
            acc[3][0] = ffma2(a23.y, b01.x, acc[3][0]);
            acc[3][1] = ffma2(a23.y, b01.y, acc[3][1]);
            acc[3][2] = ffma2(a23.y, b23.x, acc[3][2]);
            acc[3][3] = ffma2(a23.y, b23.y, acc[3][3]);
        }
        __syncthreads();
    }
#pragma unroll
    for (int i = 0; i < 4; i++) {
        int row = r0 + tm + i;
        if (row < N_NODES) {
            unsigned long long* dst =
                (unsigned long long*)(g_h + (size_t)row * DIM + tn);
            dst[0] = acc[i][0]; dst[1] = acc[i][1];
            dst[2] = acc[i][2]; dst[3] = acc[i][3];
        }
    }
}

// ---------------- elementwise: g_h = relu(g_agg + bias) ----------------
__global__ void k_bias_relu(const float* __restrict__ bias) {
    size_t i = (size_t)blockIdx.x * blockDim.x + threadIdx.x;
    if (i < (size_t)N_NODES * DIM) {
        float v = g_agg[i] + bias[i & (DIM - 1)];
        g_h[i] = fmaxf(v, 0.f);
    }
}

// ---------------- edge aggregation: one warp per destination node ----------------
__global__ __launch_bounds__(256) void k_agg() {
    int n = (blockIdx.x * blockDim.x + threadIdx.x) >> 5;
    int lane = threadIdx.x & 31;
    if (n >= N_NODES) return;
    const float4* h4 = (const float4*)g_h;
    float dn = g_dinv[n];
    float sw = dn * dn;
    float4 a = h4[(size_t)n * 32 + lane];
    float4 acc;
    acc.x = sw * a.x; acc.y = sw * a.y; acc.z = sw * a.z; acc.w = sw * a.w;
    int j = g_off[n];
    int end = j + g_cnt[n];
    for (; j + 4 <= end; j += 4) {
        int s0 = g_csr_src[j], s1 = g_csr_src[j + 1];
        int s2 = g_csr_src[j + 2], s3 = g_csr_src[j + 3];
        float w0 = g_csr_w[j], w1 = g_csr_w[j + 1];
        float w2 = g_csr_w[j + 2], w3 = g_csr_w[j + 3];
        float4 v0 = h4[(size_t)s0 * 32 + lane];
        float4 v1 = h4[(size_t)s1 * 32 + lane];
        float4 v2 = h4[(size_t)s2 * 32 + lane];
        float4 v3 = h4[(size_t)s3 * 32 + lane];
        acc.x += w0 * v0.x; acc.y += w0 * v0.y; acc.z += w0 * v0.z; acc.w += w0 * v0.w;
        acc.x += w1 * v1.x; acc.y += w1 * v1.y; acc.z += w1 * v1.z; acc.w += w1 * v1.w;
        acc.x += w2 * v2.x; acc.y += w2 * v2.y; acc.z += w2 * v2.z; acc.w += w2 * v2.w;
        acc.x += w3 * v3.x; acc.y += w3 * v3.y; acc.z += w3 * v3.z; acc.w += w3 * v3.w;
    }
    for (; j < end; j++) {
        int s = g_csr_src[j];
        float w = g_csr_w[j];
        float4 v = h4[(size_t)s * 32 + lane];
        acc.x += w * v.x; acc.y += w * v.y; acc.z += w * v.z; acc.w += w * v.w;
    }
    ((float4*)g_agg)[(size_t)n * 32 + lane] = acc;
}

// ---------------- readout: segmented sum of g_agg over sorted batch ids ----------------
#define NPB 256
__global__ void k_readout(const int* __restrict__ batch) {
    int d = threadIdx.x;  // 128 threads, one dim each
    int n0 = blockIdx.x * NPB;
    if (n0 >= N_NODES) return;
    int n1 = n0 + NPB;
    if (n1 > N_NODES) n1 = N_NODES;
    int curb = batch[n0];
    if ((unsigned)curb >= N_GRAPHS) curb = 0;
    float acc = 0.f;
    int c = 0;
    for (int n = n0; n < n1; n++) {
        int b = batch[n];
        if ((unsigned)b >= N_GRAPHS) b = 0;
        if (b != curb) {
            atomicAdd(&g_gsum[curb * DIM + d], acc);
            if (d == 0) atomicAdd(&g_gcnt[curb], (float)c);
            acc = 0.f; c = 0; curb = b;
        }
        acc += g_agg[(size_t)n * DIM + d];
        c++;
    }
    atomicAdd(&g_gsum[curb * DIM + d], acc);
    if (d == 0) atomicAdd(&g_gcnt[curb], (float)c);
}

// ---------------- final: out[g] = mean_vec(g) @ W3 + b3 (0 if empty graph) ----------
__global__ __launch_bounds__(128) void k_final(const float* __restrict__ W3,
                                               const float* __restrict__ b3,
                                               float* __restrict__ out) {
    __shared__ float m[DIM];
    int g = blockIdx.x;
    int d = threadIdx.x;
    float c = g_gcnt[g];
    float inv = (c > 0.f) ? (1.f / c) : 0.f;
    m[d] = g_gsum[g * DIM + d] * inv;
    __syncthreads();
    float acc = 0.f;
#pragma unroll 8
    for (int k = 0; k < DIM; k++)
        acc = fmaf(m[k], W3[k * DIM + d], acc);
    out[g * DIM + d] = (c > 0.f) ? (acc + b3[d]) : 0.f;
}

// ---------------- launch ----------------
extern "C" void kernel_launch(void* const* d_in, const int* in_sizes, int n_in,
                              void* d_out, int out_size) {
    (void)in_sizes; (void)n_in; (void)out_size;
    const float* x     = (const float*)d_in[0];
    const int*   ei    = (const int*)d_in[1];
    const int*   batch = (const int*)d_in[2];
    const float* W1    = (const float*)d_in[3];
    const float* b1    = (const float*)d_in[4];
    const float* W2    = (const float*)d_in[5];
    const float* b2    = (const float*)d_in[6];
    const float* W3    = (const float*)d_in[7];
    const float* b3    = (const float*)d_in[8];
    float* out = (float*)d_out;

    k_zero<<<(N_NODES + 255) / 256, 256>>>();
    k_degree<<<(N_EDGES + 255) / 256, 256>>>(ei);
    k_scan<<<1, 1024>>>();
    k_dinv<<<(N_NODES + 255) / 256, 256>>>();
    k_fill<<<(N_EDGES + 255) / 256, 256>>>(ei);

    int gemm_blocks = (N_NODES + 63) / 64;
    int agg_blocks = (N_NODES * 32 + 255) / 256;
    int ew_blocks = (int)(((size_t)N_NODES * DIM + 255) / 256);

    // layer 1: h = x @ W1 ; agg
    k_gemm<<<gemm_blocks, 256>>>(x, W1, nullptr, 0, 0);
    k_agg<<<agg_blocks, 256>>>();
    // layer 2: h = relu(agg + b1) @ W2 ; agg
    k_gemm<<<gemm_blocks, 256>>>(x, W2, b1, 1, 1);
    k_agg<<<agg_blocks, 256>>>();
    // layer 3: h = relu(agg + b2) ; agg ; (W3 applied post-pooling)
    k_bias_relu<<<ew_blocks, 256>>>(b2);
    k_agg<<<agg_blocks, 256>>>();

    k_readout<<<(N_NODES + NPB - 1) / NPB, 128>>>(batch);
    k_final<<<N_GRAPHS, 128>>>(W3, b3, out);
}

// round 5
// speedup vs baseline: 1.3900x; 1.2874x over previous
#include <cuda_runtime.h>
#include <cstdint>
#include <cstddef>

#define N_NODES  100000
#define N_EDGES  1600000
#define DIM      128
#define N_GRAPHS 512

// ---------------- scratch (static device globals; no allocation) ----------------
__device__ __align__(16) float g_h[(size_t)N_NODES * DIM];
__device__ __align__(16) float g_agg[(size_t)N_NODES * DIM];
__device__ __align__(16) float g_dinv[N_NODES];
__device__ __align__(16) int   g_cnt[N_NODES];
__device__ __align__(16) int   g_off[N_NODES];
__device__ __align__(16) int   g_cur[N_NODES];
__device__ __align__(16) int   g_csr_src[N_EDGES];
__device__ __align__(16) float g_csr_w[N_EDGES];
__device__ __align__(16) float g_gsum[N_GRAPHS * DIM];
__device__ __align__(16) float g_gcnt[N_GRAPHS];
__device__ int g_partial[32];

// ---------------- packed f32x2 helpers ----------------
__device__ __forceinline__ unsigned long long pack2(float x, float y) {
    unsigned long long r;
    asm("mov.b64 %0, {%1, %2};" : "=l"(r) : "f"(x), "f"(y));
    return r;
}
__device__ __forceinline__ unsigned long long ffma2(unsigned long long a,
                                                    unsigned long long b,
                                                    unsigned long long c) {
    unsigned long long d;
    asm("fma.rn.f32x2 %0, %1, %2, %3;" : "=l"(d) : "l"(a), "l"(b), "l"(c));
    return d;
}

// ---------------- setup kernels ----------------
__global__ void k_zero() {
    int i = blockIdx.x * blockDim.x + threadIdx.x;
    if (i < N_NODES) g_cnt[i] = 0;
    if (i < N_GRAPHS * DIM) g_gsum[i] = 0.f;
    if (i < N_GRAPHS) g_gcnt[i] = 0.f;
}

__global__ void k_degree(const int* __restrict__ ei) {
    int e4 = (blockIdx.x * blockDim.x + threadIdx.x) * 4;
    if (e4 + 3 < N_EDGES) {
        int4 d = *(const int4*)(ei + N_EDGES + e4);
        if ((unsigned)d.x < N_NODES) atomicAdd(&g_cnt[d.x], 1);
        if ((unsigned)d.y < N_NODES) atomicAdd(&g_cnt[d.y], 1);
        if ((unsigned)d.z < N_NODES) atomicAdd(&g_cnt[d.z], 1);
        if ((unsigned)d.w < N_NODES) atomicAdd(&g_cnt[d.w], 1);
    }
}

// scan stage 1: per-block local exclusive scan (4096 elems/block), emit block totals
__global__ __launch_bounds__(1024) void k_scan1() {
    __shared__ int warp_sums[32];
    int t = threadIdx.x, lane = t & 31, wid = t >> 5;
    int i0 = blockIdx.x * 4096 + t * 4;
    int v[4];
#pragma unroll
    for (int q = 0; q < 4; q++) {
        int i = i0 + q;
        v[q] = (i < N_NODES) ? g_cnt[i] : 0;
    }
    int tsum = v[0] + v[1] + v[2] + v[3];
    int x = tsum;
#pragma unroll
    for (int s = 1; s < 32; s <<= 1) {
        int y = __shfl_up_sync(0xffffffffu, x, s);
        if (lane >= s) x += y;
    }
    if (lane == 31) warp_sums[wid] = x;
    __syncthreads();
    if (wid == 0) {
        int ws = warp_sums[lane];
        int xx = ws;
#pragma unroll
        for (int s = 1; s < 32; s <<= 1) {
            int y = __shfl_up_sync(0xffffffffu, xx, s);
            if (lane >= s) xx += y;
        }
        warp_sums[lane] = xx - ws;  // exclusive warp offsets
    }
    __syncthreads();
    int run = warp_sums[wid] + (x - tsum);
#pragma unroll
    for (int q = 0; q < 4; q++) {
        int i = i0 + q;
        if (i < N_NODES) g_off[i] = run;
        run += v[q];
    }
    if (t == 1023) g_partial[blockIdx.x] = warp_sums[31] + x;
}

// scan stage 2: one warp scans the 25 block totals (exclusive, in place)
__global__ void k_scan2(int nblk) {
    int lane = threadIdx.x;
    int v = (lane < nblk) ? g_partial[lane] : 0;
    int x = v;
#pragma unroll
    for (int s = 1; s < 32; s <<= 1) {
        int y = __shfl_up_sync(0xffffffffu, x, s);
        if (lane >= s) x += y;
    }
    if (lane < nblk) g_partial[lane] = x - v;
}

// scan stage 3: add block offsets; init cursors; compute dinv
__global__ void k_scan3() {
    int i = blockIdx.x * blockDim.x + threadIdx.x;
    if (i < N_NODES) {
        int o = g_off[i] + g_partial[i >> 12];
        g_off[i] = o;
        g_cur[i] = o;
        g_dinv[i] = rsqrtf((float)g_cnt[i] + 1.0f);
    }
}

__global__ void k_fill(const int* __restrict__ ei) {
    int e4 = (blockIdx.x * blockDim.x + threadIdx.x) * 4;
    if (e4 + 3 < N_EDGES) {
        int4 s = *(const int4*)(ei + e4);
        int4 d = *(const int4*)(ei + N_EDGES + e4);
        int ss[4] = {s.x, s.y, s.z, s.w};
        int dd[4] = {d.x, d.y, d.z, d.w};
#pragma unroll
        for (int q = 0; q < 4; q++) {
            if ((unsigned)ss[q] < N_NODES && (unsigned)dd[q] < N_NODES) {
                int pos = atomicAdd(&g_cur[dd[q]], 1);
                if ((unsigned)pos < N_EDGES) {
                    g_csr_src[pos] = ss[q];
                    g_csr_w[pos] = g_dinv[ss[q]] * g_dinv[dd[q]];
                }
            }
        }
    }
}

// ---------------- GEMM: g_h = act(in + bias) @ W ----------------
// BM=128, BN=128, BK=16, 256 threads, 8x8 micro-tile, f32x2 FMAs.
__global__ __launch_bounds__(256, 2) void k_gemm(const float* __restrict__ xin,
                                                 const float* __restrict__ W,
                                                 const float* __restrict__ bias,
                                                 int use_agg_in, int do_relu) {
    __shared__ __align__(16) float As[16][132];  // [k][m], row 528B
    __shared__ __align__(16) float Bs[16][128];  // [k][n], row 512B
    const float* in = use_agg_in ? g_agg : xin;
    int r0 = blockIdx.x * 128;
    int tid = threadIdx.x;
    int tm = (tid >> 4) << 3;   // 0..120
    int tn = (tid & 15) << 3;   // 0..120
    int arow = tid >> 1;              // 0..127
    int acol = (tid & 1) << 3;        // 0 or 8
    int brow = tid >> 4;              // 0..15
    int bcol = (tid & 15) << 3;       // 0..120
    bool arow_ok = (r0 + arow) < N_NODES;
    const float* inrow = in + (size_t)(r0 + arow) * DIM;

    unsigned long long acc[8][4];
#pragma unroll
    for (int i = 0; i < 8; i++)
#pragma unroll
        for (int j = 0; j < 4; j++) acc[i][j] = 0ull;

    for (int kb = 0; kb < DIM; kb += 16) {
        // A tile: 128 rows x 16 k, transposed store, bias/relu fused
        float4 a0 = make_float4(0.f, 0.f, 0.f, 0.f), a1 = a0;
        if (arow_ok) {
            a0 = *(const float4*)(inrow + kb + acol);
            a1 = *(const float4*)(inrow + kb + acol + 4);
        }
        if (bias) {
            float4 q0 = *(const float4*)(bias + kb + acol);
            float4 q1 = *(const float4*)(bias + kb + acol + 4);
            a0.x += q0.x; a0.y += q0.y; a0.z += q0.z; a0.w += q0.w;
            a1.x += q1.x; a1.y += q1.y; a1.z += q1.z; a1.w += q1.w;
        }
        if (do_relu) {
            a0.x = fmaxf(a0.x, 0.f); a0.y = fmaxf(a0.y, 0.f);
            a0.z = fmaxf(a0.z, 0.f); a0.w = fmaxf(a0.w, 0.f);
            a1.x = fmaxf(a1.x, 0.f); a1.y = fmaxf(a1.y, 0.f);
            a1.z = fmaxf(a1.z, 0.f); a1.w = fmaxf(a1.w, 0.f);
        }
        As[acol + 0][arow] = a0.x; As[acol + 1][arow] = a0.y;
        As[acol + 2][arow] = a0.z; As[acol + 3][arow] = a0.w;
        As[acol + 4][arow] = a1.x; As[acol + 5][arow] = a1.y;
        As[acol + 6][arow] = a1.z; As[acol + 7][arow] = a1.w;
        // B tile: 16 k x 128 n
        const float* wrow = W + (size_t)(kb + brow) * DIM + bcol;
        *(float4*)&Bs[brow][bcol] = *(const float4*)(wrow);
        *(float4*)&Bs[brow][bcol + 4] = *(const float4*)(wrow + 4);
        __syncthreads();
#pragma unroll
        for (int kk = 0; kk < 16; kk++) {
            float4 af0 = *(const float4*)&As[kk][tm];
            float4 af1 = *(const float4*)&As[kk][tm + 4];
            ulonglong2 b01 = *(const ulonglong2*)&Bs[kk][tn];
            ulonglong2 b23 = *(const ulonglong2*)&Bs[kk][tn + 4];
            unsigned long long bv[4] = {b01.x, b01.y, b23.x, b23.y};
            unsigned long long ap[8];
            ap[0] = pack2(af0.x, af0.x); ap[1] = pack2(af0.y, af0.y);
            ap[2] = pack2(af0.z, af0.z); ap[3] = pack2(af0.w, af0.w);
            ap[4] = pack2(af1.x, af1.x); ap[5] = pack2(af1.y, af1.y);
            ap[6] = pack2(af1.z, af1.z); ap[7] = pack2(af1.w, af1.w);
#pragma unroll
            for (int i = 0; i < 8; i++)
#pragma unroll
                for (int j = 0; j < 4; j++)
                    acc[i][j] = ffma2(ap[i], bv[j], acc[i][j]);
        }
        __syncthreads();
    }
#pragma unroll
    for (int i = 0; i < 8; i++) {
        int row = r0 + tm + i;
        if (row < N_NODES) {
            unsigned long long* dst =
                (unsigned long long*)(g_h + (size_t)row * DIM + tn);
            dst[0] = acc[i][0]; dst[1] = acc[i][1];
            dst[2] = acc[i][2]; dst[3] = acc[i][3];
        }
    }
}

// ---------------- edge aggregation: one warp per destination node ----------------
// in/out selected by flags; optional fused relu(acc + bias) epilogue.
__global__ __launch_bounds__(256) void k_agg(int in_is_agg, int out_is_h,
                                             const float* __restrict__ bias) {
    int n = (blockIdx.x * blockDim.x + threadIdx.x) >> 5;
    int lane = threadIdx.x & 31;
    if (n >= N_NODES) return;
    const float4* h4 = (const float4*)(in_is_agg ? g_agg : g_h);
    float4* out4 = (float4*)(out_is_h ? g_h : g_agg);
    float dn = g_dinv[n];
    float sw = dn * dn;
    float4 a = h4[(size_t)n * 32 + lane];
    float4 acc;
    acc.x = sw * a.x; acc.y = sw * a.y; acc.z = sw * a.z; acc.w = sw * a.w;
    int j = g_off[n];
    int end = j + g_cnt[n];
    for (; j + 4 <= end; j += 4) {
        int s0 = g_csr_src[j], s1 = g_csr_src[j + 1];
        int s2 = g_csr_src[j + 2], s3 = g_csr_src[j + 3];
        float w0 = g_csr_w[j], w1 = g_csr_w[j + 1];
        float w2 = g_csr_w[j + 2], w3 = g_csr_w[j + 3];
        float4 v0 = h4[(size_t)s0 * 32 + lane];
        float4 v1 = h4[(size_t)s1 * 32 + lane];
        float4 v2 = h4[(size_t)s2 * 32 + lane];
        float4 v3 = h4[(size_t)s3 * 32 + lane];
        acc.x += w0 * v0.x; acc.y += w0 * v0.y; acc.z += w0 * v0.z; acc.w += w0 * v0.w;
        acc.x += w1 * v1.x; acc.y += w1 * v1.y; acc.z += w1 * v1.z; acc.w += w1 * v1.w;
        acc.x += w2 * v2.x; acc.y += w2 * v2.y; acc.z += w2 * v2.z; acc.w += w2 * v2.w;
        acc.x += w3 * v3.x; acc.y += w3 * v3.y; acc.z += w3 * v3.z; acc.w += w3 * v3.w;
    }
    for (; j < end; j++) {
        int s = g_csr_src[j];
        float w = g_csr_w[j];
        float4 v = h4[(size_t)s * 32 + lane];
        acc.x += w * v.x; acc.y += w * v.y; acc.z += w * v.z; acc.w += w * v.w;
    }
    if (bias) {
        const float4 b = *(const float4*)(bias + lane * 4);
        acc.x = fmaxf(acc.x + b.x, 0.f);
        acc.y = fmaxf(acc.y + b.y, 0.f);
        acc.z = fmaxf(acc.z + b.z, 0.f);
        acc.w = fmaxf(acc.w + b.w, 0.f);
    }
    out4[(size_t)n * 32 + lane] = acc;
}

// ---------------- readout: segmented sum of g_h over sorted batch ids ----------------
#define NPB 256
__global__ void k_readout(const int* __restrict__ batch) {
    int d = threadIdx.x;  // 128 threads, one dim each
    int n0 = blockIdx.x * NPB;
    if (n0 >= N_NODES) return;
    int n1 = n0 + NPB;
    if (n1 > N_NODES) n1 = N_NODES;
    int curb = batch[n0];
    if ((unsigned)curb >= N_GRAPHS) curb = 0;
    float acc = 0.f;
    int c = 0;
    for (int n = n0; n < n1; n++) {
        int b = batch[n];
        if ((unsigned)b >= N_GRAPHS) b = 0;
        if (b != curb) {
            atomicAdd(&g_gsum[curb * DIM + d], acc);
            if (d == 0) atomicAdd(&g_gcnt[curb], (float)c);
            acc = 0.f; c = 0; curb = b;
        }
        acc += g_h[(size_t)n * DIM + d];
        c++;
    }
    atomicAdd(&g_gsum[curb * DIM + d], acc);
    if (d == 0) atomicAdd(&g_gcnt[curb], (float)c);
}

// ---------------- final: out[g] = mean_vec(g) @ W3 + b3 (0 if empty graph) ----------
__global__ __launch_bounds__(128) void k_final(const float* __restrict__ W3,
                                               const float* __restrict__ b3,
                                               float* __restrict__ out) {
    __shared__ float m[DIM];
    int g = blockIdx.x;
    int d = threadIdx.x;
    float c = g_gcnt[g];
    float inv = (c > 0.f) ? (1.f / c) : 0.f;
    m[d] = g_gsum[g * DIM + d] * inv;
    __syncthreads();
    float acc = 0.f;
#pragma unroll 8
    for (int k = 0; k < DIM; k++)
        acc = fmaf(m[k], W3[k * DIM + d], acc);
    out[g * DIM + d] = (c > 0.f) ? (acc + b3[d]) : 0.f;
}

// ---------------- launch ----------------
extern "C" void kernel_launch(void* const* d_in, const int* in_sizes, int n_in,
                              void* d_out, int out_size) {
    (void)in_sizes; (void)n_in; (void)out_size;
    const float* x     = (const float*)d_in[0];
    const int*   ei    = (const int*)d_in[1];
    const int*   batch = (const int*)d_in[2];
    const float* W1    = (const float*)d_in[3];
    const float* b1    = (const float*)d_in[4];
    const float* W2    = (const float*)d_in[5];
    const float* b2    = (const float*)d_in[6];
    const float* W3    = (const float*)d_in[7];
    const float* b3    = (const float*)d_in[8];
    float* out = (float*)d_out;

    int scan_blocks = (N_NODES + 4095) / 4096;  // 25

    k_zero<<<(N_NODES + 255) / 256, 256>>>();
    k_degree<<<(N_EDGES / 4 + 255) / 256, 256>>>(ei);
    k_scan1<<<scan_blocks, 1024>>>();
    k_scan2<<<1, 32>>>(scan_blocks);
    k_scan3<<<(N_NODES + 255) / 256, 256>>>();
    k_fill<<<(N_EDGES / 4 + 255) / 256, 256>>>(ei);

    int gemm_blocks = (N_NODES + 127) / 128;
    int agg_blocks = (N_NODES * 32 + 255) / 256;

    // layer 1: h = x @ W1 ; agg -> g_agg
    k_gemm<<<gemm_blocks, 256>>>(x, W1, nullptr, 0, 0);
    k_agg<<<agg_blocks, 256>>>(0, 0, nullptr);
    // layer 2: h = relu(agg + b1) @ W2 ; agg -> g_agg with fused relu(.+b2)
    k_gemm<<<gemm_blocks, 256>>>(x, W2, b1, 1, 1);
    k_agg<<<agg_blocks, 256>>>(0, 0, b2);
    // layer 3: agg(g_agg) -> g_h ; W3 applied post-pooling
    k_agg<<<agg_blocks, 256>>>(1, 1, nullptr);

    k_readout<<<(N_NODES + NPB - 1) / NPB, 128>>>(batch);
    k_final<<<N_GRAPHS, 128>>>(W3, b3, out);
}

// round 6
// speedup vs baseline: 1.5828x; 1.1387x over previous
#include <cuda_runtime.h>
#include <cuda_fp16.h>
#include <cstdint>
#include <cstddef>

#define N_NODES  100000
#define N_EDGES  1600000
#define DIM      128
#define N_GRAPHS 512

// ---------------- scratch (static device globals; no allocation) ----------------
__device__ __align__(16) __half g_h16[(size_t)N_NODES * DIM];   // fp16 features (gather src)
__device__ __align__(16) __half g_h16b[(size_t)N_NODES * DIM];  // fp16 features (layer3 src)
__device__ __align__(16) float  g_agg[(size_t)N_NODES * DIM];   // fp32 aggregated
__device__ __align__(16) float  g_dinv[N_NODES];
__device__ __align__(16) int    g_cnt[N_NODES];
__device__ __align__(16) int    g_off[N_NODES];
__device__ __align__(16) int    g_cur[N_NODES];
__device__ __align__(16) int2   g_csr[N_EDGES];                 // {src, w as bits}
__device__ __align__(16) float  g_gsum[N_GRAPHS * DIM];
__device__ __align__(16) float  g_gcnt[N_GRAPHS];
__device__ int g_partial[32];

// ---------------- packed f32x2 helpers ----------------
__device__ __forceinline__ unsigned long long pack2(float x, float y) {
    unsigned long long r;
    asm("mov.b64 %0, {%1, %2};" : "=l"(r) : "f"(x), "f"(y));
    return r;
}
__device__ __forceinline__ void unpack2(unsigned long long v, float& x, float& y) {
    asm("mov.b64 {%0, %1}, %2;" : "=f"(x), "=f"(y) : "l"(v));
}
__device__ __forceinline__ unsigned long long ffma2(unsigned long long a,
                                                    unsigned long long b,
                                                    unsigned long long c) {
    unsigned long long d;
    asm("fma.rn.f32x2 %0, %1, %2, %3;" : "=l"(d) : "l"(a), "l"(b), "l"(c));
    return d;
}

// ---------------- setup kernels ----------------
__global__ void k_zero() {
    int i = blockIdx.x * blockDim.x + threadIdx.x;
    if (i < N_NODES) g_cnt[i] = 0;
    if (i < N_GRAPHS * DIM) g_gsum[i] = 0.f;
    if (i < N_GRAPHS) g_gcnt[i] = 0.f;
}

__global__ void k_degree(const int* __restrict__ ei) {
    int e4 = (blockIdx.x * blockDim.x + threadIdx.x) * 4;
    if (e4 + 3 < N_EDGES) {
        int4 d = *(const int4*)(ei + N_EDGES + e4);
        if ((unsigned)d.x < N_NODES) atomicAdd(&g_cnt[d.x], 1);
        if ((unsigned)d.y < N_NODES) atomicAdd(&g_cnt[d.y], 1);
        if ((unsigned)d.z < N_NODES) atomicAdd(&g_cnt[d.z], 1);
        if ((unsigned)d.w < N_NODES) atomicAdd(&g_cnt[d.w], 1);
    }
}

// scan stage 1: per-block local exclusive scan (4096/block), block totals, dinv
__global__ __launch_bounds__(1024) void k_scan1() {
    __shared__ int warp_sums[32];
    int t = threadIdx.x, lane = t & 31, wid = t >> 5;
    int i0 = blockIdx.x * 4096 + t * 4;
    int v[4];
#pragma unroll
    for (int q = 0; q < 4; q++) {
        int i = i0 + q;
        v[q] = (i < N_NODES) ? g_cnt[i] : 0;
        if (i < N_NODES) g_dinv[i] = rsqrtf((float)v[q] + 1.0f);
    }
    int tsum = v[0] + v[1] + v[2] + v[3];
    int x = tsum;
#pragma unroll
    for (int s = 1; s < 32; s <<= 1) {
        int y = __shfl_up_sync(0xffffffffu, x, s);
        if (lane >= s) x += y;
    }
    if (lane == 31) warp_sums[wid] = x;
    __syncthreads();
    if (wid == 0) {
        int ws = warp_sums[lane];
        int xx = ws;
#pragma unroll
        for (int s = 1; s < 32; s <<= 1) {
            int y = __shfl_up_sync(0xffffffffu, xx, s);
            if (lane >= s) xx += y;
        }
        warp_sums[lane] = xx - ws;
    }
    __syncthreads();
    int run = warp_sums[wid] + (x - tsum);
#pragma unroll
    for (int q = 0; q < 4; q++) {
        int i = i0 + q;
        if (i < N_NODES) g_off[i] = run;
        run += v[q];
    }
    if (t == 1023) g_partial[blockIdx.x] = warp_sums[31] + x;
}

// scan stage 2+3 merged: every block redundantly scans the 25 partials, adds offsets
__global__ void k_scan3(int nblk) {
    __shared__ int sp[32];
    int t = threadIdx.x;
    if (t < 32) {
        int v = (t < nblk) ? g_partial[t] : 0;
        int x = v;
#pragma unroll
        for (int s = 1; s < 32; s <<= 1) {
            int y = __shfl_up_sync(0xffffffffu, x, s);
            if ((t & 31) >= s) x += y;
        }
        sp[t] = x - v;  // exclusive
    }
    __syncthreads();
    int i = blockIdx.x * blockDim.x + t;
    if (i < N_NODES) {
        int o = g_off[i] + sp[i >> 12];
        g_off[i] = o;
        g_cur[i] = o;
    }
}

__global__ void k_fill(const int* __restrict__ ei) {
    int e4 = (blockIdx.x * blockDim.x + threadIdx.x) * 4;
    if (e4 + 3 < N_EDGES) {
        int4 s = *(const int4*)(ei + e4);
        int4 d = *(const int4*)(ei + N_EDGES + e4);
        int ss[4] = {s.x, s.y, s.z, s.w};
        int dd[4] = {d.x, d.y, d.z, d.w};
#pragma unroll
        for (int q = 0; q < 4; q++) {
            if ((unsigned)ss[q] < N_NODES && (unsigned)dd[q] < N_NODES) {
                int pos = atomicAdd(&g_cur[dd[q]], 1);
                if ((unsigned)pos < N_EDGES) {
                    float w = g_dinv[ss[q]] * g_dinv[dd[q]];
                    g_csr[pos] = make_int2(ss[q], __float_as_int(w));
                }
            }
        }
    }
}

// ---------------- GEMM: g_h16 = fp16( act(in + bias) @ W ) ----------------
// BM=128, BN=128, BK=16, 256 threads, 8x8 micro-tile, f32x2 FMAs.
__global__ __launch_bounds__(256, 2) void k_gemm(const float* __restrict__ xin,
                                                 const float* __restrict__ W,
                                                 const float* __restrict__ bias,
                                                 int use_agg_in, int do_relu) {
    __shared__ __align__(16) float As[16][132];
    __shared__ __align__(16) float Bs[16][128];
    const float* in = use_agg_in ? g_agg : xin;
    int r0 = blockIdx.x * 128;
    int tid = threadIdx.x;
    int tm = (tid >> 4) << 3;
    int tn = (tid & 15) << 3;
    int arow = tid >> 1;
    int acol = (tid & 1) << 3;
    int brow = tid >> 4;
    int bcol = (tid & 15) << 3;
    bool arow_ok = (r0 + arow) < N_NODES;
    const float* inrow = in + (size_t)(r0 + arow) * DIM;

    unsigned long long acc[8][4];
#pragma unroll
    for (int i = 0; i < 8; i++)
#pragma unroll
        for (int j = 0; j < 4; j++) acc[i][j] = 0ull;

    for (int kb = 0; kb < DIM; kb += 16) {
        float4 a0 = make_float4(0.f, 0.f, 0.f, 0.f), a1 = a0;
        if (arow_ok) {
            a0 = *(const float4*)(inrow + kb + acol);
            a1 = *(const float4*)(inrow + kb + acol + 4);
        }
        if (bias) {
            float4 q0 = *(const float4*)(bias + kb + acol);
            float4 q1 = *(const float4*)(bias + kb + acol + 4);
            a0.x += q0.x; a0.y += q0.y; a0.z += q0.z; a0.w += q0.w;
            a1.x += q1.x; a1.y += q1.y; a1.z += q1.z; a1.w += q1.w;
        }
        if (do_relu) {
            a0.x = fmaxf(a0.x, 0.f); a0.y = fmaxf(a0.y, 0.f);
            a0.z = fmaxf(a0.z, 0.f); a0.w = fmaxf(a0.w, 0.f);
            a1.x = fmaxf(a1.x, 0.f); a1.y = fmaxf(a1.y, 0.f);
            a1.z = fmaxf(a1.z, 0.f); a1.w = fmaxf(a1.w, 0.f);
        }
        As[acol + 0][arow] = a0.x; As[acol + 1][arow] = a0.y;
        As[acol + 2][arow] = a0.z; As[acol + 3][arow] = a0.w;
        As[acol + 4][arow] = a1.x; As[acol + 5][arow] = a1.y;
        As[acol + 6][arow] = a1.z; As[acol + 7][arow] = a1.w;
        const float* wrow = W + (size_t)(kb + brow) * DIM + bcol;
        *(float4*)&Bs[brow][bcol] = *(const float4*)(wrow);
        *(float4*)&Bs[brow][bcol + 4] = *(const float4*)(wrow + 4);
        __syncthreads();
#pragma unroll
        for (int kk = 0; kk < 16; kk++) {
            float4 af0 = *(const float4*)&As[kk][tm];
            float4 af1 = *(const float4*)&As[kk][tm + 4];
            ulonglong2 b01 = *(const ulonglong2*)&Bs[kk][tn];
            ulonglong2 b23 = *(const ulonglong2*)&Bs[kk][tn + 4];
            unsigned long long bv[4] = {b01.x, b01.y, b23.x, b23.y};
            unsigned long long ap[8];
            ap[0] = pack2(af0.x, af0.x); ap[1] = pack2(af0.y, af0.y);
            ap[2] = pack2(af0.z, af0.z); ap[3] = pack2(af0.w, af0.w);
            ap[4] = pack2(af1.x, af1.x); ap[5] = pack2(af1.y, af1.y);
            ap[6] = pack2(af1.z, af1.z); ap[7] = pack2(af1.w, af1.w);
#pragma unroll
            for (int i = 0; i < 8; i++)
#pragma unroll
                for (int j = 0; j < 4; j++)
                    acc[i][j] = ffma2(ap[i], bv[j], acc[i][j]);
        }
        __syncthreads();
    }
#pragma unroll
    for (int i = 0; i < 8; i++) {
        int row = r0 + tm + i;
        if (row < N_NODES) {
            uint4 o;
            float lo, hi;
            unpack2(acc[i][0], lo, hi);
            __half2 h0 = __floats2half2_rn(lo, hi);
            unpack2(acc[i][1], lo, hi);
            __half2 h1 = __floats2half2_rn(lo, hi);
            unpack2(acc[i][2], lo, hi);
            __half2 h2 = __floats2half2_rn(lo, hi);
            unpack2(acc[i][3], lo, hi);
            __half2 h3 = __floats2half2_rn(lo, hi);
            o.x = *(unsigned*)&h0; o.y = *(unsigned*)&h1;
            o.z = *(unsigned*)&h2; o.w = *(unsigned*)&h3;
            *(uint4*)(g_h16 + (size_t)row * DIM + tn) = o;
        }
    }
}

// ---------------- edge aggregation (fp16 gather): one warp per dest node ----------
// in_sel: 0 = g_h16, 1 = g_h16b.  out_f16: 0 -> g_agg (fp32), 1 -> g_h16b (fp16).
__global__ __launch_bounds__(256) void k_agg(int in_sel, int out_f16,
                                             const float* __restrict__ bias) {
    int n = (blockIdx.x * blockDim.x + threadIdx.x) >> 5;
    int lane = threadIdx.x & 31;
    if (n >= N_NODES) return;
    const uint2* in2 = (const uint2*)(in_sel ? g_h16b : g_h16);
    float dn = g_dinv[n];
    float sw = dn * dn;
    uint2 sv = in2[(size_t)n * 32 + lane];
    __half2 sp0 = *(__half2*)&sv.x, sp1 = *(__half2*)&sv.y;
    float2 sf0 = __half22float2(sp0), sf1 = __half22float2(sp1);
    float4 acc;
    acc.x = sw * sf0.x; acc.y = sw * sf0.y; acc.z = sw * sf1.x; acc.w = sw * sf1.y;
    int j = g_off[n];
    int end = j + g_cnt[n];
    for (; j + 4 <= end; j += 4) {
        int2 e0 = g_csr[j], e1 = g_csr[j + 1], e2 = g_csr[j + 2], e3 = g_csr[j + 3];
        float w0 = __int_as_float(e0.y), w1 = __int_as_float(e1.y);
        float w2 = __int_as_float(e2.y), w3 = __int_as_float(e3.y);
        uint2 r0 = in2[(size_t)e0.x * 32 + lane];
        uint2 r1 = in2[(size_t)e1.x * 32 + lane];
        uint2 r2 = in2[(size_t)e2.x * 32 + lane];
        uint2 r3 = in2[(size_t)e3.x * 32 + lane];
        float2 f0a = __half22float2(*(__half2*)&r0.x), f0b = __half22float2(*(__half2*)&r0.y);
        float2 f1a = __half22float2(*(__half2*)&r1.x), f1b = __half22float2(*(__half2*)&r1.y);
        float2 f2a = __half22float2(*(__half2*)&r2.x), f2b = __half22float2(*(__half2*)&r2.y);
        float2 f3a = __half22float2(*(__half2*)&r3.x), f3b = __half22float2(*(__half2*)&r3.y);
        acc.x += w0 * f0a.x; acc.y += w0 * f0a.y; acc.z += w0 * f0b.x; acc.w += w0 * f0b.y;
        acc.x += w1 * f1a.x; acc.y += w1 * f1a.y; acc.z += w1 * f1b.x; acc.w += w1 * f1b.y;
        acc.x += w2 * f2a.x; acc.y += w2 * f2a.y; acc.z += w2 * f2b.x; acc.w += w2 * f2b.y;
        acc.x += w3 * f3a.x; acc.y += w3 * f3a.y; acc.z += w3 * f3b.x; acc.w += w3 * f3b.y;
    }
    for (; j < end; j++) {
        int2 e = g_csr[j];
        float w = __int_as_float(e.y);
        uint2 r = in2[(size_t)e.x * 32 + lane];
        float2 fa = __half22float2(*(__half2*)&r.x), fb = __half22float2(*(__half2*)&r.y);
        acc.x += w * fa.x; acc.y += w * fa.y; acc.z += w * fb.x; acc.w += w * fb.y;
    }
    if (bias) {
        const float4 b = *(const float4*)(bias + lane * 4);
        acc.x = fmaxf(acc.x + b.x, 0.f);
        acc.y = fmaxf(acc.y + b.y, 0.f);
        acc.z = fmaxf(acc.z + b.z, 0.f);
        acc.w = fmaxf(acc.w + b.w, 0.f);
    }
    if (out_f16) {
        __half2 o0 = __floats2half2_rn(acc.x, acc.y);
        __half2 o1 = __floats2half2_rn(acc.z, acc.w);
        uint2 ov;
        ov.x = *(unsigned*)&o0; ov.y = *(unsigned*)&o1;
        ((uint2*)g_h16b)[(size_t)n * 32 + lane] = ov;
    } else {
        ((float4*)g_agg)[(size_t)n * 32 + lane] = acc;
    }
}

// ---------------- readout: segmented sum of g_agg over sorted batch ids ----------
#define NPB 256
__global__ void k_readout(const int* __restrict__ batch) {
    int d = threadIdx.x;
    int n0 = blockIdx.x * NPB;
    if (n0 >= N_NODES) return;
    int n1 = n0 + NPB;
    if (n1 > N_NODES) n1 = N_NODES;
    int curb = batch[n0];
    if ((unsigned)curb >= N_GRAPHS) curb = 0;
    float acc = 0.f;
    int c = 0;
    for (int n = n0; n < n1; n++) {
        int b = batch[n];
        if ((unsigned)b >= N_GRAPHS) b = 0;
        if (b != curb) {
            atomicAdd(&g_gsum[curb * DIM + d], acc);
            if (d == 0) atomicAdd(&g_gcnt[curb], (float)c);
            acc = 0.f; c = 0; curb = b;
        }
        acc += g_agg[(size_t)n * DIM + d];
        c++;
    }
    atomicAdd(&g_gsum[curb * DIM + d], acc);
    if (d == 0) atomicAdd(&g_gcnt[curb], (float)c);
}

// ---------------- final: out[g] = mean_vec(g) @ W3 + b3 (0 if empty graph) --------
__global__ __launch_bounds__(128) void k_final(const float* __restrict__ W3,
                                               const float* __restrict__ b3,
                                               float* __restrict__ out) {
    __shared__ float m[DIM];
    int g = blockIdx.x;
    int d = threadIdx.x;
    float c = g_gcnt[g];
    float inv = (c > 0.f) ? (1.f / c) : 0.f;
    m[d] = g_gsum[g * DIM + d] * inv;
    __syncthreads();
    float acc = 0.f;
#pragma unroll 8
    for (int k = 0; k < DIM; k++)
        acc = fmaf(m[k], W3[k * DIM + d], acc);
    out[g * DIM + d] = (c > 0.f) ? (acc + b3[d]) : 0.f;
}

// ---------------- launch ----------------
extern "C" void kernel_launch(void* const* d_in, const int* in_sizes, int n_in,
                              void* d_out, int out_size) {
    (void)in_sizes; (void)n_in; (void)out_size;
    const float* x     = (const float*)d_in[0];
    const int*   ei    = (const int*)d_in[1];
    const int*   batch = (const int*)d_in[2];
    const float* W1    = (const float*)d_in[3];
    const float* b1    = (const float*)d_in[4];
    const float* W2    = (const float*)d_in[5];
    const float* b2    = (const float*)d_in[6];
    const float* W3    = (const float*)d_in[7];
    const float* b3    = (const float*)d_in[8];
    float* out = (float*)d_out;

    int scan_blocks = (N_NODES + 4095) / 4096;  // 25

    k_zero<<<(N_NODES + 255) / 256, 256>>>();
    k_degree<<<(N_EDGES / 4 + 255) / 256, 256>>>(ei);
    k_scan1<<<scan_blocks, 1024>>>();
    k_scan3<<<(N_NODES + 255) / 256, 256>>>(scan_blocks);
    k_fill<<<(N_EDGES / 4 + 255) / 256, 256>>>(ei);

    int gemm_blocks = (N_NODES + 127) / 128;
    int agg_blocks = (N_NODES * 32 + 255) / 256;

    // layer 1: h16 = fp16(x @ W1) ; agg -> g_agg (fp32)
    k_gemm<<<gemm_blocks, 256>>>(x, W1, nullptr, 0, 0);
    k_agg<<<agg_blocks, 256>>>(0, 0, nullptr);
    // layer 2: h16 = fp16(relu(agg + b1) @ W2) ; agg -> g_h16b with fused relu(.+b2)
    k_gemm<<<gemm_blocks, 256>>>(x, W2, b1, 1, 1);
    k_agg<<<agg_blocks, 256>>>(0, 1, b2);
    // layer 3: agg(g_h16b) -> g_agg (fp32) ; W3 applied post-pooling
    k_agg<<<agg_blocks, 256>>>(1, 0, nullptr);

    k_readout<<<(N_NODES + NPB - 1) / NPB, 128>>>(batch);
    k_final<<<N_GRAPHS, 128>>>(W3, b3, out);
}